// round 8
// baseline (speedup 1.0000x reference)
#include <cuda_runtime.h>
#include <cuda_bf16.h>
#include <math.h>
#include <stdint.h>

// ---------------- problem constants ----------------
constexpr int B_ = 8, C_ = 512, H_ = 96, W_ = 96;
constexpr int N_ = H_ * W_;    // 9216
constexpr int O3 = 3 * C_;     // 1536

// ---------------- scratch: bf16 hi/lo planes ----------------
__device__ __align__(256) __nv_bfloat16 g_qh [(size_t)B_ * O3 * N_];
__device__ __align__(256) __nv_bfloat16 g_ql [(size_t)B_ * O3 * N_];
__device__ __align__(256) __nv_bfloat16 g_xTh[(size_t)B_ * N_ * C_];  // reused as o1T
__device__ __align__(256) __nv_bfloat16 g_xTl[(size_t)B_ * N_ * C_];
__device__ __align__(256) __nv_bfloat16 g_vTh[(size_t)B_ * N_ * C_];
__device__ __align__(256) __nv_bfloat16 g_vTl[(size_t)B_ * N_ * C_];
__device__ __align__(256) float         g_S  [(size_t)B_ * C_ * C_];
__device__ __align__(256) __nv_bfloat16 g_ah [(size_t)B_ * C_ * C_];
__device__ __align__(256) __nv_bfloat16 g_al [(size_t)B_ * C_ * C_];
__device__ __align__(256) __nv_bfloat16 g_wqh[(size_t)O3 * C_];
__device__ __align__(256) __nv_bfloat16 g_wql[(size_t)O3 * C_];
__device__ __align__(256) __nv_bfloat16 g_wph[(size_t)C_ * C_];
__device__ __align__(256) __nv_bfloat16 g_wpl[(size_t)C_ * C_];

// ---------------- common helpers ----------------
#define BK 32
#define LDT 40   // smem row stride in bf16 (BK + 8 pad)

__device__ __forceinline__ uint32_t smem_u32(const void* p) {
    uint32_t a;
    asm("{ .reg .u64 t; cvta.to.shared.u64 t, %1; cvt.u32.u64 %0, t; }"
        : "=r"(a) : "l"(p));
    return a;
}
__device__ __forceinline__ void cp16(uint32_t dst, const void* src) {
    asm volatile("cp.async.cg.shared.global [%0], [%1], 16;"
                 :: "r"(dst), "l"(src));
}
__device__ __forceinline__ void mma16816(float* d, const uint32_t* a,
                                         const uint32_t* b) {
    asm volatile(
        "mma.sync.aligned.m16n8k16.row.col.f32.bf16.bf16.f32 "
        "{%0,%1,%2,%3}, {%4,%5,%6,%7}, {%8,%9}, {%0,%1,%2,%3};"
        : "+f"(d[0]), "+f"(d[1]), "+f"(d[2]), "+f"(d[3])
        : "r"(a[0]), "r"(a[1]), "r"(a[2]), "r"(a[3]), "r"(b[0]), "r"(b[1]));
}
__device__ __forceinline__ void ldm4(uint32_t* r, uint32_t a) {
    asm volatile("ldmatrix.sync.aligned.m8n8.x4.shared.b16 {%0,%1,%2,%3}, [%4];"
        : "=r"(r[0]), "=r"(r[1]), "=r"(r[2]), "=r"(r[3]) : "r"(a));
}
__device__ __forceinline__ uint32_t pack2(__nv_bfloat16 a, __nv_bfloat16 b) {
    return (uint32_t)__bfloat16_as_ushort(a) |
           ((uint32_t)__bfloat16_as_ushort(b) << 16);
}

// lane offsets (bf16 elem units) for ldmatrix addressing
__device__ __forceinline__ int laneA_off(int lane) {
    return ((lane & 7) + ((lane >> 3) & 1) * 8) * LDT + ((lane >> 4) & 1) * 8;
}
__device__ __forceinline__ int laneB_off(int lane) {
    return ((lane & 7) + ((lane >> 4) & 1) * 8) * LDT + ((lane >> 3) & 1) * 8;
}

// ================ unified GEMM: 128x128, 256 thr, 2-stage, 2 CTA/SM =======
#define P_AH 0
#define P_AL (128 * LDT)
#define P_BH (256 * LDT)
#define P_BL (384 * LDT)
#define STAGE_EL (512 * LDT)
#define STAGE_BY (STAGE_EL * 2)              // 40960 B
#define NST 2
#define SMEM_BY (NST * STAGE_BY)             // 81920 B -> 2 CTAs/SM

template<bool HASBIAS, bool SPLITOUT>
__global__ __launch_bounds__(256, 2)
void gemm_u(const __nv_bfloat16* __restrict__ Ah, const __nv_bfloat16* __restrict__ Al,
            const __nv_bfloat16* __restrict__ Bh, const __nv_bfloat16* __restrict__ Bl,
            float* __restrict__ Cf,
            __nv_bfloat16* __restrict__ Ch, __nv_bfloat16* __restrict__ Cl,
            const float* __restrict__ bias,
            int K, int lda, int ldb, int ldc,
            size_t sA_, size_t sB_, size_t sC_)
{
    extern __shared__ __nv_bfloat16 smem[];
    const int tid  = threadIdx.x;
    const int warp = tid >> 5;
    const int lane = tid & 31;
    const int wm   = (warp >> 2) * 64;   // 2 warps in M
    const int wn   = (warp & 3) * 32;    // 4 warps in N
    const int tm   = blockIdx.y * 128;
    const int tn   = blockIdx.x * 128;

    const __nv_bfloat16* Ahb = Ah + (size_t)blockIdx.z * sA_;
    const __nv_bfloat16* Alb = Al + (size_t)blockIdx.z * sA_;
    const __nv_bfloat16* Bhb = Bh + (size_t)blockIdx.z * sB_;
    const __nv_bfloat16* Blb = Bl + (size_t)blockIdx.z * sB_;

    const int lrow = tid >> 1;
    const int lg   = (tid & 1) * 16;
    const __nv_bfloat16* pAh = Ahb + (size_t)(tm + lrow) * lda + lg;
    const __nv_bfloat16* pAl = Alb + (size_t)(tm + lrow) * lda + lg;
    const __nv_bfloat16* pBh = Bhb + (size_t)(tn + lrow) * ldb + lg;
    const __nv_bfloat16* pBl = Blb + (size_t)(tn + lrow) * ldb + lg;
    const uint32_t sbase = smem_u32(smem);
    const uint32_t doff  = (lrow * LDT + lg) * 2;

    const int lA = laneA_off(lane);
    const int lB = laneB_off(lane);

    float acc[4][4][4];
    #pragma unroll
    for (int i = 0; i < 4; i++)
        #pragma unroll
        for (int j = 0; j < 4; j++)
            #pragma unroll
            for (int t = 0; t < 4; t++) acc[i][j][t] = 0.f;

    auto issue = [&](int c) {
        const uint32_t sb = sbase + (c & 1) * STAGE_BY + doff;
        const int k0 = c * BK;
        cp16(sb + P_AH * 2,      pAh + k0);
        cp16(sb + P_AH * 2 + 16, pAh + k0 + 8);
        cp16(sb + P_AL * 2,      pAl + k0);
        cp16(sb + P_AL * 2 + 16, pAl + k0 + 8);
        cp16(sb + P_BH * 2,      pBh + k0);
        cp16(sb + P_BH * 2 + 16, pBh + k0 + 8);
        cp16(sb + P_BL * 2,      pBl + k0);
        cp16(sb + P_BL * 2 + 16, pBl + k0 + 8);
    };

    const int nc = K / BK;
    issue(0);
    asm volatile("cp.async.commit_group;");

    for (int c = 0; c < nc; ++c) {
        asm volatile("cp.async.wait_group 0;");
        __syncthreads();
        if (c + 1 < nc) issue(c + 1);
        asm volatile("cp.async.commit_group;");

        const uint32_t stb = sbase + (c & 1) * STAGE_BY;
        #pragma unroll
        for (int ks = 0; ks < 2; ++ks) {
            const int kofs = ks * 16;
            uint32_t ah[4][4], al_[4][4];
            #pragma unroll
            for (int i = 0; i < 4; i++) {
                uint32_t ao = ((wm + i * 16) * LDT + lA + kofs) * 2;
                ldm4(ah[i],  stb + P_AH * 2 + ao);
                ldm4(al_[i], stb + P_AL * 2 + ao);
            }
            #pragma unroll
            for (int jp = 0; jp < 2; ++jp) {
                uint32_t bo = ((wn + jp * 16) * LDT + lB + kofs) * 2;
                uint32_t bh[4], bl_[4];
                ldm4(bh,  stb + P_BH * 2 + bo);
                ldm4(bl_, stb + P_BL * 2 + bo);
                const int j0 = jp * 2, j1 = jp * 2 + 1;
                #pragma unroll
                for (int i = 0; i < 4; i++) { mma16816(acc[i][j0], ah[i],  bh);     }
                #pragma unroll
                for (int i = 0; i < 4; i++) { mma16816(acc[i][j1], ah[i],  bh + 2); }
                #pragma unroll
                for (int i = 0; i < 4; i++) { mma16816(acc[i][j0], al_[i], bh);     }
                #pragma unroll
                for (int i = 0; i < 4; i++) { mma16816(acc[i][j1], al_[i], bh + 2); }
                #pragma unroll
                for (int i = 0; i < 4; i++) { mma16816(acc[i][j0], ah[i],  bl_);    }
                #pragma unroll
                for (int i = 0; i < 4; i++) { mma16816(acc[i][j1], ah[i],  bl_ + 2);}
            }
        }
    }

    // ---------------- epilogue ----------------
    #pragma unroll
    for (int i = 0; i < 4; i++) {
        const int r0 = tm + wm + i * 16 + (lane >> 2);
        float bv0 = 0.f, bv1 = 0.f;
        if (HASBIAS) { bv0 = bias[r0]; bv1 = bias[r0 + 8]; }
        #pragma unroll
        for (int j = 0; j < 4; j++) {
            const int cc = tn + wn + j * 8 + (lane & 3) * 2;
            float d0 = acc[i][j][0] + bv0, d1 = acc[i][j][1] + bv0;
            float d2 = acc[i][j][2] + bv1, d3 = acc[i][j][3] + bv1;
            if (SPLITOUT) {
                __nv_bfloat16* chp = Ch + (size_t)blockIdx.z * sC_;
                __nv_bfloat16* clp = Cl + (size_t)blockIdx.z * sC_;
                __nv_bfloat16 h0 = __float2bfloat16(d0), h1 = __float2bfloat16(d1);
                __nv_bfloat16 h2 = __float2bfloat16(d2), h3 = __float2bfloat16(d3);
                __nv_bfloat16 l0 = __float2bfloat16(d0 - __bfloat162float(h0));
                __nv_bfloat16 l1 = __float2bfloat16(d1 - __bfloat162float(h1));
                __nv_bfloat16 l2 = __float2bfloat16(d2 - __bfloat162float(h2));
                __nv_bfloat16 l3 = __float2bfloat16(d3 - __bfloat162float(h3));
                *reinterpret_cast<uint32_t*>(&chp[(size_t)r0 * ldc + cc])       = pack2(h0, h1);
                *reinterpret_cast<uint32_t*>(&clp[(size_t)r0 * ldc + cc])       = pack2(l0, l1);
                *reinterpret_cast<uint32_t*>(&chp[(size_t)(r0 + 8) * ldc + cc]) = pack2(h2, h3);
                *reinterpret_cast<uint32_t*>(&clp[(size_t)(r0 + 8) * ldc + cc]) = pack2(l2, l3);
            } else {
                float* cfp = Cf + (size_t)blockIdx.z * sC_;
                *reinterpret_cast<float2*>(&cfp[(size_t)r0 * ldc + cc])       = make_float2(d0, d1);
                *reinterpret_cast<float2*>(&cfp[(size_t)(r0 + 8) * ldc + cc]) = make_float2(d2, d3);
            }
        }
    }
}

// ---------------- transpose + split: fp32 [R,Cc] -> bf16 hi/lo [Cc,R] ------
__global__ void transpose_split(const float* __restrict__ in,
                                __nv_bfloat16* __restrict__ oh,
                                __nv_bfloat16* __restrict__ ol,
                                int R, int Cc, size_t sIn, size_t sOut)
{
    __shared__ float t[32][33];
    const float* ip = in + (size_t)blockIdx.z * sIn;
    int r0 = blockIdx.y * 32, c0 = blockIdx.x * 32;
    #pragma unroll
    for (int j = threadIdx.y; j < 32; j += 8)
        t[j][threadIdx.x] = ip[(size_t)(r0 + j) * Cc + c0 + threadIdx.x];
    __syncthreads();
    #pragma unroll
    for (int j = threadIdx.y; j < 32; j += 8) {
        float f = t[threadIdx.x][j];
        __nv_bfloat16 h = __float2bfloat16(f);
        __nv_bfloat16 l = __float2bfloat16(f - __bfloat162float(h));
        size_t idx = (size_t)blockIdx.z * sOut + (size_t)(c0 + j) * R + r0 + threadIdx.x;
        oh[idx] = h;
        ol[idx] = l;
    }
}

// ---------------- transpose two bf16 planes: [R,Cc] -> [Cc,R] --------------
__global__ void transpose_b2(const __nv_bfloat16* __restrict__ ih,
                             const __nv_bfloat16* __restrict__ il,
                             __nv_bfloat16* __restrict__ oh,
                             __nv_bfloat16* __restrict__ ol,
                             int R, int Cc, size_t sIn, size_t sOut)
{
    __shared__ __nv_bfloat16 th[32][34], tl[32][34];
    const __nv_bfloat16* ihp = ih + (size_t)blockIdx.z * sIn;
    const __nv_bfloat16* ilp = il + (size_t)blockIdx.z * sIn;
    int r0 = blockIdx.y * 32, c0 = blockIdx.x * 32;
    #pragma unroll
    for (int j = threadIdx.y; j < 32; j += 8) {
        size_t s = (size_t)(r0 + j) * Cc + c0 + threadIdx.x;
        th[j][threadIdx.x] = ihp[s];
        tl[j][threadIdx.x] = ilp[s];
    }
    __syncthreads();
    #pragma unroll
    for (int j = threadIdx.y; j < 32; j += 8) {
        size_t d = (size_t)blockIdx.z * sOut + (size_t)(c0 + j) * R + r0 + threadIdx.x;
        oh[d] = th[threadIdx.x][j];
        ol[d] = tl[threadIdx.x][j];
    }
}

// ---------------- elementwise split fp32 -> bf16 hi/lo ---------------------
__global__ void split_w(const float* __restrict__ in,
                        __nv_bfloat16* __restrict__ oh,
                        __nv_bfloat16* __restrict__ ol, int n)
{
    int i = blockIdx.x * blockDim.x + threadIdx.x;
    if (i >= n) return;
    float f = in[i];
    __nv_bfloat16 h = __float2bfloat16(f);
    oh[i] = h;
    ol[i] = __float2bfloat16(f - __bfloat162float(h));
}

// ---------------- softmax (fp32 in, bf16 hi/lo out), rows of 512 -----------
__global__ void softmax_split(const float* __restrict__ S,
                              __nv_bfloat16* __restrict__ oh,
                              __nv_bfloat16* __restrict__ ol, float scale)
{
    int warp = (blockIdx.x * blockDim.x + threadIdx.x) >> 5;
    int lane = threadIdx.x & 31;
    if (warp >= B_ * C_) return;
    const float* row = S + (size_t)warp * C_;

    float vals[C_ / 32];
    float m = -1e30f;
    #pragma unroll
    for (int t = 0; t < C_ / 32; t++) {
        vals[t] = row[lane + t * 32] * scale;
        m = fmaxf(m, vals[t]);
    }
    #pragma unroll
    for (int o = 16; o; o >>= 1) m = fmaxf(m, __shfl_xor_sync(0xffffffffu, m, o));
    float s = 0.f;
    #pragma unroll
    for (int t = 0; t < C_ / 32; t++) { vals[t] = __expf(vals[t] - m); s += vals[t]; }
    #pragma unroll
    for (int o = 16; o; o >>= 1) s += __shfl_xor_sync(0xffffffffu, s, o);
    float inv = 1.f / s;
    #pragma unroll
    for (int t = 0; t < C_ / 32; t++) {
        float p = vals[t] * inv;
        __nv_bfloat16 h = __float2bfloat16(p);
        size_t idx = (size_t)warp * C_ + lane + t * 32;
        oh[idx] = h;
        ol[idx] = __float2bfloat16(p - __bfloat162float(h));
    }
}

// ---------------- launcher ----------------
extern "C" void kernel_launch(void* const* d_in, const int* in_sizes, int n_in,
                              void* d_out, int out_size)
{
    const float* x      = (const float*)d_in[0];
    const float* w_qkv  = (const float*)d_in[1];
    const float* b_qkv  = (const float*)d_in[2];
    const float* w_proj = (const float*)d_in[3];
    const float* b_proj = (const float*)d_in[4];
    float* out = (float*)d_out;

    __nv_bfloat16 *qh, *ql, *xTh, *xTl, *vTh, *vTl, *ah, *al, *wqh, *wql, *wph, *wpl;
    float *S;
    cudaGetSymbolAddress((void**)&qh,  g_qh);
    cudaGetSymbolAddress((void**)&ql,  g_ql);
    cudaGetSymbolAddress((void**)&xTh, g_xTh);
    cudaGetSymbolAddress((void**)&xTl, g_xTl);
    cudaGetSymbolAddress((void**)&vTh, g_vTh);
    cudaGetSymbolAddress((void**)&vTl, g_vTl);
    cudaGetSymbolAddress((void**)&S,   g_S);
    cudaGetSymbolAddress((void**)&ah,  g_ah);
    cudaGetSymbolAddress((void**)&al,  g_al);
    cudaGetSymbolAddress((void**)&wqh, g_wqh);
    cudaGetSymbolAddress((void**)&wql, g_wql);
    cudaGetSymbolAddress((void**)&wph, g_wph);
    cudaGetSymbolAddress((void**)&wpl, g_wpl);

    cudaFuncSetAttribute(gemm_u<true,  true>,  cudaFuncAttributeMaxDynamicSharedMemorySize, SMEM_BY);
    cudaFuncSetAttribute(gemm_u<false, true>,  cudaFuncAttributeMaxDynamicSharedMemorySize, SMEM_BY);
    cudaFuncSetAttribute(gemm_u<true,  false>, cudaFuncAttributeMaxDynamicSharedMemorySize, SMEM_BY);
    cudaFuncSetAttribute(gemm_u<false, false>, cudaFuncAttributeMaxDynamicSharedMemorySize, SMEM_BY);

    const float scale = 1.0f / sqrtf((float)C_);
    dim3 tblk(32, 8);

    // 0) split weights
    split_w<<<(O3 * C_ + 255) / 256, 256>>>(w_qkv, wqh, wql, O3 * C_);
    split_w<<<(C_ * C_ + 255) / 256, 256>>>(w_proj, wph, wpl, C_ * C_);

    // 1) xT hi/lo: x[b,c,n] -> [b,n,c]
    transpose_split<<<dim3(N_ / 32, C_ / 32, B_), tblk>>>(
        x, xTh, xTl, C_, N_, (size_t)C_ * N_, (size_t)N_ * C_);

    // 2) qkv = w_qkv @ xT^T + b  -> bf16 hi/lo [b,1536,9216]
    gemm_u<true, true><<<dim3(N_ / 128, O3 / 128, B_), 256, SMEM_BY>>>(
        wqh, wql, xTh, xTl, nullptr, qh, ql, b_qkv,
        C_, C_, C_, N_,
        0, (size_t)N_ * C_, (size_t)O3 * N_);

    // 3) vT hi/lo: v[b,d,n] -> [b,n,d]
    transpose_b2<<<dim3(N_ / 32, C_ / 32, B_), tblk>>>(
        qh + (size_t)2 * C_ * N_, ql + (size_t)2 * C_ * N_, vTh, vTl,
        C_, N_, (size_t)O3 * N_, (size_t)N_ * C_);

    // 4) S = q @ k^T (fp32), K=9216
    gemm_u<false, false><<<dim3(C_ / 128, C_ / 128, B_), 256, SMEM_BY>>>(
        qh, ql, qh + (size_t)C_ * N_, ql + (size_t)C_ * N_,
        S, nullptr, nullptr, nullptr,
        N_, N_, N_, C_,
        (size_t)O3 * N_, (size_t)O3 * N_, (size_t)C_ * C_);

    // 5) softmax -> attn hi/lo
    softmax_split<<<(B_ * C_ * 32 + 255) / 256, 256>>>(S, ah, al, scale);

    // 6) o1T[b,n,c] = vT[b,n,:] @ attn[b,c,:]  -> bf16 hi/lo (reuse xT buffers)
    gemm_u<false, true><<<dim3(C_ / 128, N_ / 128, B_), 256, SMEM_BY>>>(
        vTh, vTl, ah, al, nullptr, xTh, xTl, nullptr,
        C_, C_, C_, C_,
        (size_t)N_ * C_, (size_t)C_ * C_, (size_t)N_ * C_);

    // 7) out = w_proj @ o1T^T + b (fp32)
    gemm_u<true, false><<<dim3(N_ / 128, C_ / 128, B_), 256, SMEM_BY>>>(
        wph, wpl, xTh, xTl, out, nullptr, nullptr, b_proj,
        C_, C_, C_, N_,
        0, (size_t)N_ * C_, (size_t)C_ * N_);
}

// round 9
// speedup vs baseline: 1.0207x; 1.0207x over previous
#include <cuda_runtime.h>
#include <cuda_bf16.h>
#include <math.h>
#include <stdint.h>

// ---------------- problem constants ----------------
constexpr int B_ = 8, C_ = 512, H_ = 96, W_ = 96;
constexpr int N_ = H_ * W_;    // 9216
constexpr int O3 = 3 * C_;     // 1536

// ---------------- scratch: bf16 hi/lo planes ----------------
__device__ __align__(256) __nv_bfloat16 g_qh [(size_t)B_ * O3 * N_];
__device__ __align__(256) __nv_bfloat16 g_ql [(size_t)B_ * O3 * N_];
__device__ __align__(256) __nv_bfloat16 g_xTh[(size_t)B_ * N_ * C_];  // reused as o1T
__device__ __align__(256) __nv_bfloat16 g_xTl[(size_t)B_ * N_ * C_];
__device__ __align__(256) __nv_bfloat16 g_vTh[(size_t)B_ * N_ * C_];
__device__ __align__(256) __nv_bfloat16 g_vTl[(size_t)B_ * N_ * C_];
__device__ __align__(256) float         g_S  [(size_t)B_ * C_ * C_];
__device__ __align__(256) __nv_bfloat16 g_ah [(size_t)B_ * C_ * C_];
__device__ __align__(256) __nv_bfloat16 g_al [(size_t)B_ * C_ * C_];
__device__ __align__(256) __nv_bfloat16 g_wqh[(size_t)O3 * C_];
__device__ __align__(256) __nv_bfloat16 g_wql[(size_t)O3 * C_];
__device__ __align__(256) __nv_bfloat16 g_wph[(size_t)C_ * C_];
__device__ __align__(256) __nv_bfloat16 g_wpl[(size_t)C_ * C_];

// ---------------- common helpers ----------------
#define BK 32
#define LDT 40   // smem row stride in bf16 (BK + 8 pad)

__device__ __forceinline__ uint32_t smem_u32(const void* p) {
    uint32_t a;
    asm("{ .reg .u64 t; cvta.to.shared.u64 t, %1; cvt.u32.u64 %0, t; }"
        : "=r"(a) : "l"(p));
    return a;
}
__device__ __forceinline__ void cp16(uint32_t dst, const void* src) {
    asm volatile("cp.async.cg.shared.global [%0], [%1], 16;"
                 :: "r"(dst), "l"(src));
}
__device__ __forceinline__ void mma16816(float* d, const uint32_t* a,
                                         const uint32_t* b) {
    asm volatile(
        "mma.sync.aligned.m16n8k16.row.col.f32.bf16.bf16.f32 "
        "{%0,%1,%2,%3}, {%4,%5,%6,%7}, {%8,%9}, {%0,%1,%2,%3};"
        : "+f"(d[0]), "+f"(d[1]), "+f"(d[2]), "+f"(d[3])
        : "r"(a[0]), "r"(a[1]), "r"(a[2]), "r"(a[3]), "r"(b[0]), "r"(b[1]));
}
__device__ __forceinline__ void ldm4(uint32_t* r, uint32_t a) {
    asm volatile("ldmatrix.sync.aligned.m8n8.x4.shared.b16 {%0,%1,%2,%3}, [%4];"
        : "=r"(r[0]), "=r"(r[1]), "=r"(r[2]), "=r"(r[3]) : "r"(a));
}
__device__ __forceinline__ uint32_t pack2(__nv_bfloat16 a, __nv_bfloat16 b) {
    return (uint32_t)__bfloat16_as_ushort(a) |
           ((uint32_t)__bfloat16_as_ushort(b) << 16);
}

// lane offsets (bf16 elem units) for ldmatrix addressing
__device__ __forceinline__ int laneA_off(int lane) {
    return ((lane & 7) + ((lane >> 3) & 1) * 8) * LDT + ((lane >> 4) & 1) * 8;
}
__device__ __forceinline__ int laneB_off(int lane) {
    return ((lane & 7) + ((lane >> 4) & 1) * 8) * LDT + ((lane >> 3) & 1) * 8;
}

// Shared per-(chunk,ks) compute body: 3 passes (hh, lh, hl) with fragment
// prefetch interleaved into the MMA streams. All asm volatile -> source order
// is the schedule.
//   aBase/bBase: smem byte addr of A-hi / B-hi plane origin for this warp+ks
//   planeOff:    byte distance from hi plane to lo plane
__device__ __forceinline__ void compute_ks(float acc[4][4][4],
                                           uint32_t aHi, uint32_t aLo,
                                           uint32_t bHi, uint32_t bLo)
{
    uint32_t ah[4][4], al_[4][4], bh[2][4], bl_[2][4];
    // entry burst: A-hi (4) + B-hi (2)
    #pragma unroll
    for (int i = 0; i < 4; i++) ldm4(ah[i], aHi + i * (16 * LDT * 2));
    #pragma unroll
    for (int jp = 0; jp < 2; jp++) ldm4(bh[jp], bHi + jp * (16 * LDT * 2));

    // HH pass (16 MMAs), prefetch A-lo interleaved
    #pragma unroll
    for (int i = 0; i < 4; i++) {
        ldm4(al_[i], aLo + i * (16 * LDT * 2));
        mma16816(acc[i][0], ah[i], bh[0]);
        mma16816(acc[i][1], ah[i], bh[0] + 2);
        mma16816(acc[i][2], ah[i], bh[1]);
        mma16816(acc[i][3], ah[i], bh[1] + 2);
    }
    // LH pass (16 MMAs), prefetch B-lo interleaved
    #pragma unroll
    for (int i = 0; i < 4; i++) {
        if (i < 2) ldm4(bl_[i], bLo + i * (16 * LDT * 2));
        mma16816(acc[i][0], al_[i], bh[0]);
        mma16816(acc[i][1], al_[i], bh[0] + 2);
        mma16816(acc[i][2], al_[i], bh[1]);
        mma16816(acc[i][3], al_[i], bh[1] + 2);
    }
    // HL pass (16 MMAs)
    #pragma unroll
    for (int i = 0; i < 4; i++) {
        mma16816(acc[i][0], ah[i], bl_[0]);
        mma16816(acc[i][1], ah[i], bl_[0] + 2);
        mma16816(acc[i][2], ah[i], bl_[1]);
        mma16816(acc[i][3], ah[i], bl_[1] + 2);
    }
}

// ================= BIG kernel: 128(M) x 256(N), 512 threads, 3-stage ======
#define BM2 128
#define BN2 256
#define NST2 3
#define P_AH 0
#define P_AL (128 * LDT)
#define P_BH (256 * LDT)
#define P_BL (512 * LDT)
#define STAGE_EL2 (768 * LDT)
#define STAGE_BY2 (STAGE_EL2 * 2)             // 61440 B
#define SMEM_BY2 (NST2 * STAGE_BY2)           // 184320 B

template<bool HASBIAS, bool SPLITOUT>
__global__ __launch_bounds__(512)
void gemm_big(const __nv_bfloat16* __restrict__ Ah, const __nv_bfloat16* __restrict__ Al,
              const __nv_bfloat16* __restrict__ Bh, const __nv_bfloat16* __restrict__ Bl,
              float* __restrict__ Cf,
              __nv_bfloat16* __restrict__ Ch, __nv_bfloat16* __restrict__ Cl,
              const float* __restrict__ bias,
              int K, int lda, int ldb, int ldc,
              size_t sA_, size_t sB_, size_t sC_)
{
    extern __shared__ __nv_bfloat16 smem[];
    const int tid  = threadIdx.x;
    const int warp = tid >> 5;
    const int lane = tid & 31;
    const int wm   = (warp >> 3) * 64;   // 2 warps in M
    const int wn   = (warp & 7) * 32;    // 8 warps in N
    const int tm   = blockIdx.y * BM2;
    const int tn   = blockIdx.x * BN2;

    const __nv_bfloat16* Ahb = Ah + (size_t)blockIdx.z * sA_;
    const __nv_bfloat16* Alb = Al + (size_t)blockIdx.z * sA_;
    const __nv_bfloat16* Bhb = Bh + (size_t)blockIdx.z * sB_;
    const __nv_bfloat16* Blb = Bl + (size_t)blockIdx.z * sB_;

    const int arow0 = tid >> 2, ag0 = (tid & 3) * 8;
    const int brow1 = tid >> 2, bg1 = (tid & 3) * 8;
    const int brow2 = (tid + 512) >> 2, bg2 = bg1;

    const __nv_bfloat16* pAh  = Ahb + (size_t)(tm + arow0) * lda + ag0;
    const __nv_bfloat16* pAl  = Alb + (size_t)(tm + arow0) * lda + ag0;
    const __nv_bfloat16* pB1h = Bhb + (size_t)(tn + brow1) * ldb + bg1;
    const __nv_bfloat16* pB1l = Blb + (size_t)(tn + brow1) * ldb + bg1;
    const __nv_bfloat16* pB2h = Bhb + (size_t)(tn + brow2) * ldb + bg2;
    const __nv_bfloat16* pB2l = Blb + (size_t)(tn + brow2) * ldb + bg2;

    const uint32_t sbase = smem_u32(smem);
    const uint32_t dA  = (arow0 * LDT + ag0) * 2;
    const uint32_t dB1 = (brow1 * LDT + bg1) * 2;
    const uint32_t dB2 = (brow2 * LDT + bg2) * 2;

    const int lA = laneA_off(lane);
    const int lB = laneB_off(lane);

    float acc[4][4][4];
    #pragma unroll
    for (int i = 0; i < 4; i++)
        #pragma unroll
        for (int j = 0; j < 4; j++)
            #pragma unroll
            for (int t = 0; t < 4; t++) acc[i][j][t] = 0.f;

    auto issue = [&](int c) {
        const uint32_t sb = sbase + (c % NST2) * STAGE_BY2;
        const int k0 = c * BK;
        cp16(sb + P_AH * 2 + dA,  pAh + k0);
        cp16(sb + P_AL * 2 + dA,  pAl + k0);
        cp16(sb + P_BH * 2 + dB1, pB1h + k0);
        cp16(sb + P_BL * 2 + dB1, pB1l + k0);
        cp16(sb + P_BH * 2 + dB2, pB2h + k0);
        cp16(sb + P_BL * 2 + dB2, pB2l + k0);
    };

    const int nc = K / BK;
    issue(0);
    asm volatile("cp.async.commit_group;");
    issue(1);
    asm volatile("cp.async.commit_group;");

    for (int c = 0; c < nc; ++c) {
        asm volatile("cp.async.wait_group 1;");
        __syncthreads();
        if (c + 2 < nc) issue(c + 2);
        asm volatile("cp.async.commit_group;");

        const uint32_t stb = sbase + (c % NST2) * STAGE_BY2;
        const uint32_t aH0 = stb + P_AH * 2 + (wm * LDT + lA) * 2;
        const uint32_t aL0 = stb + P_AL * 2 + (wm * LDT + lA) * 2;
        const uint32_t bH0 = stb + P_BH * 2 + (wn * LDT + lB) * 2;
        const uint32_t bL0 = stb + P_BL * 2 + (wn * LDT + lB) * 2;
        #pragma unroll
        for (int ks = 0; ks < 2; ++ks) {
            const uint32_t ko = ks * 32;   // 16 bf16 = 32 bytes
            compute_ks(acc, aH0 + ko, aL0 + ko, bH0 + ko, bL0 + ko);
        }
    }

    // ---------------- epilogue ----------------
    #pragma unroll
    for (int i = 0; i < 4; i++) {
        const int r0 = tm + wm + i * 16 + (lane >> 2);
        float bv0 = 0.f, bv1 = 0.f;
        if (HASBIAS) { bv0 = bias[r0]; bv1 = bias[r0 + 8]; }
        #pragma unroll
        for (int j = 0; j < 4; j++) {
            const int cc = tn + wn + j * 8 + (lane & 3) * 2;
            float d0 = acc[i][j][0] + bv0, d1 = acc[i][j][1] + bv0;
            float d2 = acc[i][j][2] + bv1, d3 = acc[i][j][3] + bv1;
            if (SPLITOUT) {
                __nv_bfloat16* chp = Ch + (size_t)blockIdx.z * sC_;
                __nv_bfloat16* clp = Cl + (size_t)blockIdx.z * sC_;
                __nv_bfloat16 h0 = __float2bfloat16(d0), h1 = __float2bfloat16(d1);
                __nv_bfloat16 h2 = __float2bfloat16(d2), h3 = __float2bfloat16(d3);
                __nv_bfloat16 l0 = __float2bfloat16(d0 - __bfloat162float(h0));
                __nv_bfloat16 l1 = __float2bfloat16(d1 - __bfloat162float(h1));
                __nv_bfloat16 l2 = __float2bfloat16(d2 - __bfloat162float(h2));
                __nv_bfloat16 l3 = __float2bfloat16(d3 - __bfloat162float(h3));
                *reinterpret_cast<uint32_t*>(&chp[(size_t)r0 * ldc + cc])       = pack2(h0, h1);
                *reinterpret_cast<uint32_t*>(&clp[(size_t)r0 * ldc + cc])       = pack2(l0, l1);
                *reinterpret_cast<uint32_t*>(&chp[(size_t)(r0 + 8) * ldc + cc]) = pack2(h2, h3);
                *reinterpret_cast<uint32_t*>(&clp[(size_t)(r0 + 8) * ldc + cc]) = pack2(l2, l3);
            } else {
                float* cfp = Cf + (size_t)blockIdx.z * sC_;
                *reinterpret_cast<float2*>(&cfp[(size_t)r0 * ldc + cc])       = make_float2(d0, d1);
                *reinterpret_cast<float2*>(&cfp[(size_t)(r0 + 8) * ldc + cc]) = make_float2(d2, d3);
            }
        }
    }
}

// ================= S kernel: 128x128, 256 threads, 2-stage ================
#define SP_AH 0
#define SP_AL (128 * LDT)
#define SP_BH (256 * LDT)
#define SP_BL (384 * LDT)
#define STAGE_ELS (512 * LDT)
#define STAGE_BYS (STAGE_ELS * 2)             // 40960 B
#define NSTS 2
#define SMEM_BYS (NSTS * STAGE_BYS)           // 81920 B

__global__ __launch_bounds__(256)
void gemm_s(const __nv_bfloat16* __restrict__ Ah, const __nv_bfloat16* __restrict__ Al,
            const __nv_bfloat16* __restrict__ Bh, const __nv_bfloat16* __restrict__ Bl,
            float* __restrict__ Cf,
            int K, int lda, int ldb, int ldc,
            size_t sA_, size_t sB_, size_t sC_)
{
    extern __shared__ __nv_bfloat16 smem[];
    const int tid  = threadIdx.x;
    const int warp = tid >> 5;
    const int lane = tid & 31;
    const int wm   = (warp >> 2) * 64;
    const int wn   = (warp & 3) * 32;
    const int tm   = blockIdx.y * 128;
    const int tn   = blockIdx.x * 128;

    const __nv_bfloat16* Ahb = Ah + (size_t)blockIdx.z * sA_;
    const __nv_bfloat16* Alb = Al + (size_t)blockIdx.z * sA_;
    const __nv_bfloat16* Bhb = Bh + (size_t)blockIdx.z * sB_;
    const __nv_bfloat16* Blb = Bl + (size_t)blockIdx.z * sB_;

    const int lrow = tid >> 1;
    const int lg   = (tid & 1) * 16;
    const __nv_bfloat16* pAh = Ahb + (size_t)(tm + lrow) * lda + lg;
    const __nv_bfloat16* pAl = Alb + (size_t)(tm + lrow) * lda + lg;
    const __nv_bfloat16* pBh = Bhb + (size_t)(tn + lrow) * ldb + lg;
    const __nv_bfloat16* pBl = Blb + (size_t)(tn + lrow) * ldb + lg;
    const uint32_t sbase = smem_u32(smem);
    const uint32_t doff  = (lrow * LDT + lg) * 2;

    const int lA = laneA_off(lane);
    const int lB = laneB_off(lane);

    float acc[4][4][4];
    #pragma unroll
    for (int i = 0; i < 4; i++)
        #pragma unroll
        for (int j = 0; j < 4; j++)
            #pragma unroll
            for (int t = 0; t < 4; t++) acc[i][j][t] = 0.f;

    auto issue = [&](int c) {
        const uint32_t sb = sbase + (c & 1) * STAGE_BYS + doff;
        const int k0 = c * BK;
        cp16(sb + SP_AH * 2,      pAh + k0);
        cp16(sb + SP_AH * 2 + 16, pAh + k0 + 8);
        cp16(sb + SP_AL * 2,      pAl + k0);
        cp16(sb + SP_AL * 2 + 16, pAl + k0 + 8);
        cp16(sb + SP_BH * 2,      pBh + k0);
        cp16(sb + SP_BH * 2 + 16, pBh + k0 + 8);
        cp16(sb + SP_BL * 2,      pBl + k0);
        cp16(sb + SP_BL * 2 + 16, pBl + k0 + 8);
    };

    const int nc = K / BK;
    issue(0);
    asm volatile("cp.async.commit_group;");

    for (int c = 0; c < nc; ++c) {
        asm volatile("cp.async.wait_group 0;");
        __syncthreads();
        if (c + 1 < nc) issue(c + 1);
        asm volatile("cp.async.commit_group;");

        const uint32_t stb = sbase + (c & 1) * STAGE_BYS;
        const uint32_t aH0 = stb + SP_AH * 2 + (wm * LDT + lA) * 2;
        const uint32_t aL0 = stb + SP_AL * 2 + (wm * LDT + lA) * 2;
        const uint32_t bH0 = stb + SP_BH * 2 + (wn * LDT + lB) * 2;
        const uint32_t bL0 = stb + SP_BL * 2 + (wn * LDT + lB) * 2;
        #pragma unroll
        for (int ks = 0; ks < 2; ++ks) {
            const uint32_t ko = ks * 32;
            compute_ks(acc, aH0 + ko, aL0 + ko, bH0 + ko, bL0 + ko);
        }
    }

    float* cfp = Cf + (size_t)blockIdx.z * sC_;
    #pragma unroll
    for (int i = 0; i < 4; i++) {
        const int r0 = tm + wm + i * 16 + (lane >> 2);
        #pragma unroll
        for (int j = 0; j < 4; j++) {
            const int cc = tn + wn + j * 8 + (lane & 3) * 2;
            *reinterpret_cast<float2*>(&cfp[(size_t)r0 * ldc + cc]) =
                make_float2(acc[i][j][0], acc[i][j][1]);
            *reinterpret_cast<float2*>(&cfp[(size_t)(r0 + 8) * ldc + cc]) =
                make_float2(acc[i][j][2], acc[i][j][3]);
        }
    }
}

// ---------------- transpose + split: fp32 [R,Cc] -> bf16 hi/lo [Cc,R] ------
__global__ void transpose_split(const float* __restrict__ in,
                                __nv_bfloat16* __restrict__ oh,
                                __nv_bfloat16* __restrict__ ol,
                                int R, int Cc, size_t sIn, size_t sOut)
{
    __shared__ float t[32][33];
    const float* ip = in + (size_t)blockIdx.z * sIn;
    int r0 = blockIdx.y * 32, c0 = blockIdx.x * 32;
    #pragma unroll
    for (int j = threadIdx.y; j < 32; j += 8)
        t[j][threadIdx.x] = ip[(size_t)(r0 + j) * Cc + c0 + threadIdx.x];
    __syncthreads();
    #pragma unroll
    for (int j = threadIdx.y; j < 32; j += 8) {
        float f = t[threadIdx.x][j];
        __nv_bfloat16 h = __float2bfloat16(f);
        __nv_bfloat16 l = __float2bfloat16(f - __bfloat162float(h));
        size_t idx = (size_t)blockIdx.z * sOut + (size_t)(c0 + j) * R + r0 + threadIdx.x;
        oh[idx] = h;
        ol[idx] = l;
    }
}

// ---------------- transpose two bf16 planes: [R,Cc] -> [Cc,R] --------------
__global__ void transpose_b2(const __nv_bfloat16* __restrict__ ih,
                             const __nv_bfloat16* __restrict__ il,
                             __nv_bfloat16* __restrict__ oh,
                             __nv_bfloat16* __restrict__ ol,
                             int R, int Cc, size_t sIn, size_t sOut)
{
    __shared__ __nv_bfloat16 th[32][34], tl[32][34];
    const __nv_bfloat16* ihp = ih + (size_t)blockIdx.z * sIn;
    const __nv_bfloat16* ilp = il + (size_t)blockIdx.z * sIn;
    int r0 = blockIdx.y * 32, c0 = blockIdx.x * 32;
    #pragma unroll
    for (int j = threadIdx.y; j < 32; j += 8) {
        size_t s = (size_t)(r0 + j) * Cc + c0 + threadIdx.x;
        th[j][threadIdx.x] = ihp[s];
        tl[j][threadIdx.x] = ilp[s];
    }
    __syncthreads();
    #pragma unroll
    for (int j = threadIdx.y; j < 32; j += 8) {
        size_t d = (size_t)blockIdx.z * sOut + (size_t)(c0 + j) * R + r0 + threadIdx.x;
        oh[d] = th[threadIdx.x][j];
        ol[d] = tl[threadIdx.x][j];
    }
}

// ---------------- elementwise split fp32 -> bf16 hi/lo ---------------------
__global__ void split_w(const float* __restrict__ in,
                        __nv_bfloat16* __restrict__ oh,
                        __nv_bfloat16* __restrict__ ol, int n)
{
    int i = blockIdx.x * blockDim.x + threadIdx.x;
    if (i >= n) return;
    float f = in[i];
    __nv_bfloat16 h = __float2bfloat16(f);
    oh[i] = h;
    ol[i] = __float2bfloat16(f - __bfloat162float(h));
}

// ---------------- softmax (fp32 in, bf16 hi/lo out), rows of 512 -----------
__global__ void softmax_split(const float* __restrict__ S,
                              __nv_bfloat16* __restrict__ oh,
                              __nv_bfloat16* __restrict__ ol, float scale)
{
    int warp = (blockIdx.x * blockDim.x + threadIdx.x) >> 5;
    int lane = threadIdx.x & 31;
    if (warp >= B_ * C_) return;
    const float* row = S + (size_t)warp * C_;

    float vals[C_ / 32];
    float m = -1e30f;
    #pragma unroll
    for (int t = 0; t < C_ / 32; t++) {
        vals[t] = row[lane + t * 32] * scale;
        m = fmaxf(m, vals[t]);
    }
    #pragma unroll
    for (int o = 16; o; o >>= 1) m = fmaxf(m, __shfl_xor_sync(0xffffffffu, m, o));
    float s = 0.f;
    #pragma unroll
    for (int t = 0; t < C_ / 32; t++) { vals[t] = __expf(vals[t] - m); s += vals[t]; }
    #pragma unroll
    for (int o = 16; o; o >>= 1) s += __shfl_xor_sync(0xffffffffu, s, o);
    float inv = 1.f / s;
    #pragma unroll
    for (int t = 0; t < C_ / 32; t++) {
        float p = vals[t] * inv;
        __nv_bfloat16 h = __float2bfloat16(p);
        size_t idx = (size_t)warp * C_ + lane + t * 32;
        oh[idx] = h;
        ol[idx] = __float2bfloat16(p - __bfloat162float(h));
    }
}

// ---------------- launcher ----------------
extern "C" void kernel_launch(void* const* d_in, const int* in_sizes, int n_in,
                              void* d_out, int out_size)
{
    const float* x      = (const float*)d_in[0];
    const float* w_qkv  = (const float*)d_in[1];
    const float* b_qkv  = (const float*)d_in[2];
    const float* w_proj = (const float*)d_in[3];
    const float* b_proj = (const float*)d_in[4];
    float* out = (float*)d_out;

    __nv_bfloat16 *qh, *ql, *xTh, *xTl, *vTh, *vTl, *ah, *al, *wqh, *wql, *wph, *wpl;
    float *S;
    cudaGetSymbolAddress((void**)&qh,  g_qh);
    cudaGetSymbolAddress((void**)&ql,  g_ql);
    cudaGetSymbolAddress((void**)&xTh, g_xTh);
    cudaGetSymbolAddress((void**)&xTl, g_xTl);
    cudaGetSymbolAddress((void**)&vTh, g_vTh);
    cudaGetSymbolAddress((void**)&vTl, g_vTl);
    cudaGetSymbolAddress((void**)&S,   g_S);
    cudaGetSymbolAddress((void**)&ah,  g_ah);
    cudaGetSymbolAddress((void**)&al,  g_al);
    cudaGetSymbolAddress((void**)&wqh, g_wqh);
    cudaGetSymbolAddress((void**)&wql, g_wql);
    cudaGetSymbolAddress((void**)&wph, g_wph);
    cudaGetSymbolAddress((void**)&wpl, g_wpl);

    cudaFuncSetAttribute(gemm_big<true,  true>,  cudaFuncAttributeMaxDynamicSharedMemorySize, SMEM_BY2);
    cudaFuncSetAttribute(gemm_big<false, true>,  cudaFuncAttributeMaxDynamicSharedMemorySize, SMEM_BY2);
    cudaFuncSetAttribute(gemm_big<true,  false>, cudaFuncAttributeMaxDynamicSharedMemorySize, SMEM_BY2);
    cudaFuncSetAttribute(gemm_s, cudaFuncAttributeMaxDynamicSharedMemorySize, SMEM_BYS);

    const float scale = 1.0f / sqrtf((float)C_);
    dim3 tblk(32, 8);

    // 0) split weights
    split_w<<<(O3 * C_ + 255) / 256, 256>>>(w_qkv, wqh, wql, O3 * C_);
    split_w<<<(C_ * C_ + 255) / 256, 256>>>(w_proj, wph, wpl, C_ * C_);

    // 1) xT hi/lo: x[b,c,n] -> [b,n,c]
    transpose_split<<<dim3(N_ / 32, C_ / 32, B_), tblk>>>(
        x, xTh, xTl, C_, N_, (size_t)C_ * N_, (size_t)N_ * C_);

    // 2) qkv = w_qkv @ xT^T + b  -> bf16 hi/lo [b,1536,9216]
    gemm_big<true, true><<<dim3(N_ / BN2, O3 / BM2, B_), 512, SMEM_BY2>>>(
        wqh, wql, xTh, xTl, nullptr, qh, ql, b_qkv,
        C_, C_, C_, N_,
        0, (size_t)N_ * C_, (size_t)O3 * N_);

    // 3) vT hi/lo: v[b,d,n] -> [b,n,d]
    transpose_b2<<<dim3(N_ / 32, C_ / 32, B_), tblk>>>(
        qh + (size_t)2 * C_ * N_, ql + (size_t)2 * C_ * N_, vTh, vTl,
        C_, N_, (size_t)O3 * N_, (size_t)N_ * C_);

    // 4) S = q @ k^T (fp32), K=9216
    gemm_s<<<dim3(C_ / 128, C_ / 128, B_), 256, SMEM_BYS>>>(
        qh, ql, qh + (size_t)C_ * N_, ql + (size_t)C_ * N_, S,
        N_, N_, N_, C_,
        (size_t)O3 * N_, (size_t)O3 * N_, (size_t)C_ * C_);

    // 5) softmax -> attn hi/lo
    softmax_split<<<(B_ * C_ * 32 + 255) / 256, 256>>>(S, ah, al, scale);

    // 6) o1T[b,n,c] = vT[b,n,:] @ attn[b,c,:]  -> bf16 hi/lo (reuse xT buffers)
    gemm_big<false, true><<<dim3(C_ / BN2, N_ / BM2, B_), 512, SMEM_BY2>>>(
        vTh, vTl, ah, al, nullptr, xTh, xTl, nullptr,
        C_, C_, C_, C_,
        (size_t)N_ * C_, (size_t)C_ * C_, (size_t)N_ * C_);

    // 7) out = w_proj @ o1T^T + b (fp32)
    gemm_big<true, false><<<dim3(N_ / BN2, C_ / BM2, B_), 512, SMEM_BY2>>>(
        wph, wpl, xTh, xTl, out, nullptr, nullptr, b_proj,
        C_, C_, C_, N_,
        0, (size_t)N_ * C_, (size_t)C_ * N_);
}

// round 10
// speedup vs baseline: 1.2969x; 1.2706x over previous
#include <cuda_runtime.h>
#include <cuda_fp16.h>
#include <math.h>
#include <stdint.h>

// ---------------- problem constants ----------------
constexpr int B_ = 8, C_ = 512, H_ = 96, W_ = 96;
constexpr int N_ = H_ * W_;    // 9216
constexpr int O3 = 3 * C_;     // 1536

// ---------------- scratch: fp16 planes ----------------
__device__ __align__(256) __half g_qh [(size_t)B_ * O3 * N_];   // qkv hi
__device__ __align__(256) __half g_ql [(size_t)B_ * O3 * N_];   // qkv lo
__device__ __align__(256) __half g_xTh[(size_t)B_ * N_ * C_];   // xT hi; later o1T hi
__device__ __align__(256) __half g_vTh[(size_t)B_ * N_ * C_];
__device__ __align__(256) __half g_vTl[(size_t)B_ * N_ * C_];
__device__ __align__(256) float  g_S  [(size_t)B_ * C_ * C_];
__device__ __align__(256) __half g_ah [(size_t)B_ * C_ * C_];   // attn hi
__device__ __align__(256) __half g_wqh[(size_t)O3 * C_];
__device__ __align__(256) __half g_wql[(size_t)O3 * C_];
__device__ __align__(256) __half g_wph[(size_t)C_ * C_];
__device__ __align__(256) __half g_wpl[(size_t)C_ * C_];

// ---------------- common helpers ----------------
#define BK 32
#define LDT 40   // smem row stride in halves (BK + 8 pad)

__device__ __forceinline__ uint32_t smem_u32(const void* p) {
    uint32_t a;
    asm("{ .reg .u64 t; cvta.to.shared.u64 t, %1; cvt.u32.u64 %0, t; }"
        : "=r"(a) : "l"(p));
    return a;
}
__device__ __forceinline__ void cp16(uint32_t dst, const void* src) {
    asm volatile("cp.async.cg.shared.global [%0], [%1], 16;"
                 :: "r"(dst), "l"(src));
}
__device__ __forceinline__ void mma16816(float* d, const uint32_t* a,
                                         const uint32_t* b) {
    asm volatile(
        "mma.sync.aligned.m16n8k16.row.col.f32.f16.f16.f32 "
        "{%0,%1,%2,%3}, {%4,%5,%6,%7}, {%8,%9}, {%0,%1,%2,%3};"
        : "+f"(d[0]), "+f"(d[1]), "+f"(d[2]), "+f"(d[3])
        : "r"(a[0]), "r"(a[1]), "r"(a[2]), "r"(a[3]), "r"(b[0]), "r"(b[1]));
}
__device__ __forceinline__ void ldm4(uint32_t* r, uint32_t a) {
    asm volatile("ldmatrix.sync.aligned.m8n8.x4.shared.b16 {%0,%1,%2,%3}, [%4];"
        : "=r"(r[0]), "=r"(r[1]), "=r"(r[2]), "=r"(r[3]) : "r"(a));
}
__device__ __forceinline__ uint32_t pack2h(__half a, __half b) {
    return (uint32_t)__half_as_ushort(a) |
           ((uint32_t)__half_as_ushort(b) << 16);
}
__device__ __forceinline__ void split2h(float f, __half& h, __half& l) {
    h = __float2half(f);
    l = __float2half(f - __half2float(h));
}

// lane offsets (half elem units) for ldmatrix addressing
__device__ __forceinline__ int laneA_off(int lane) {
    return ((lane & 7) + ((lane >> 3) & 1) * 8) * LDT + ((lane >> 4) & 1) * 8;
}
__device__ __forceinline__ int laneB_off(int lane) {
    return ((lane & 7) + ((lane >> 4) & 1) * 8) * LDT + ((lane >> 3) & 1) * 8;
}

// 2-pass compute body: (ah + al) * bh
__device__ __forceinline__ void compute_ks2(float acc[4][4][4],
                                            uint32_t aHi, uint32_t aLo,
                                            uint32_t bHi)
{
    uint32_t ah[4][4], al_[4][4], bh[2][4];
    #pragma unroll
    for (int i = 0; i < 4; i++) ldm4(ah[i], aHi + i * (16 * LDT * 2));
    #pragma unroll
    for (int jp = 0; jp < 2; jp++) ldm4(bh[jp], bHi + jp * (16 * LDT * 2));
    #pragma unroll
    for (int i = 0; i < 4; i++) {
        ldm4(al_[i], aLo + i * (16 * LDT * 2));
        mma16816(acc[i][0], ah[i], bh[0]);
        mma16816(acc[i][1], ah[i], bh[0] + 2);
        mma16816(acc[i][2], ah[i], bh[1]);
        mma16816(acc[i][3], ah[i], bh[1] + 2);
    }
    #pragma unroll
    for (int i = 0; i < 4; i++) {
        mma16816(acc[i][0], al_[i], bh[0]);
        mma16816(acc[i][1], al_[i], bh[0] + 2);
        mma16816(acc[i][2], al_[i], bh[1]);
        mma16816(acc[i][3], al_[i], bh[1] + 2);
    }
}

// 3-pass compute body (hh, lh, hl) for the S GEMM
__device__ __forceinline__ void compute_ks3(float acc[4][4][4],
                                            uint32_t aHi, uint32_t aLo,
                                            uint32_t bHi, uint32_t bLo)
{
    uint32_t ah[4][4], al_[4][4], bh[2][4], bl_[2][4];
    #pragma unroll
    for (int i = 0; i < 4; i++) ldm4(ah[i], aHi + i * (16 * LDT * 2));
    #pragma unroll
    for (int jp = 0; jp < 2; jp++) ldm4(bh[jp], bHi + jp * (16 * LDT * 2));
    #pragma unroll
    for (int i = 0; i < 4; i++) {
        ldm4(al_[i], aLo + i * (16 * LDT * 2));
        mma16816(acc[i][0], ah[i], bh[0]);
        mma16816(acc[i][1], ah[i], bh[0] + 2);
        mma16816(acc[i][2], ah[i], bh[1]);
        mma16816(acc[i][3], ah[i], bh[1] + 2);
    }
    #pragma unroll
    for (int i = 0; i < 4; i++) {
        if (i < 2) ldm4(bl_[i], bLo + i * (16 * LDT * 2));
        mma16816(acc[i][0], al_[i], bh[0]);
        mma16816(acc[i][1], al_[i], bh[0] + 2);
        mma16816(acc[i][2], al_[i], bh[1]);
        mma16816(acc[i][3], al_[i], bh[1] + 2);
    }
    #pragma unroll
    for (int i = 0; i < 4; i++) {
        mma16816(acc[i][0], ah[i], bl_[0]);
        mma16816(acc[i][1], ah[i], bl_[0] + 2);
        mma16816(acc[i][2], ah[i], bl_[1]);
        mma16816(acc[i][3], ah[i], bl_[1] + 2);
    }
}

// ============== BIG kernel: 128x256, 512 thr, 3-stage, 2-pass =============
// OUTMODE: 0 = f32, 1 = split hi/lo fp16, 2 = hi-only fp16
#define BM2 128
#define BN2 256
#define NST2 3
#define Q_AH 0
#define Q_AL (128 * LDT)
#define Q_BH (256 * LDT)
#define STAGE_EL2 (512 * LDT)
#define STAGE_BY2 (STAGE_EL2 * 2)             // 40960 B
#define SMEM_BY2 (NST2 * STAGE_BY2)           // 122880 B

template<bool HASBIAS, int OUTMODE>
__global__ __launch_bounds__(512)
void gemm_big(const __half* __restrict__ Ah, const __half* __restrict__ Al,
              const __half* __restrict__ Bh,
              float* __restrict__ Cf,
              __half* __restrict__ Ch, __half* __restrict__ Cl,
              const float* __restrict__ bias,
              int K, int lda, int ldb, int ldc,
              size_t sA_, size_t sB_, size_t sC_)
{
    extern __shared__ __half smem[];
    const int tid  = threadIdx.x;
    const int warp = tid >> 5;
    const int lane = tid & 31;
    const int wm   = (warp >> 3) * 64;   // 2 warps in M
    const int wn   = (warp & 7) * 32;    // 8 warps in N
    const int tm   = blockIdx.y * BM2;
    const int tn   = blockIdx.x * BN2;

    const __half* Ahb = Ah + (size_t)blockIdx.z * sA_;
    const __half* Alb = Al + (size_t)blockIdx.z * sA_;
    const __half* Bhb = Bh + (size_t)blockIdx.z * sB_;

    const int arow = tid >> 2, ag = (tid & 3) * 8;

    const __half* pAh  = Ahb + (size_t)(tm + arow) * lda + ag;
    const __half* pAl  = Alb + (size_t)(tm + arow) * lda + ag;
    const __half* pB1h = Bhb + (size_t)(tn + arow) * ldb + ag;
    const __half* pB2h = Bhb + (size_t)(tn + 128 + arow) * ldb + ag;

    const uint32_t sbase = smem_u32(smem);
    const uint32_t dA  = (arow * LDT + ag) * 2;
    const uint32_t dB2 = ((arow + 128) * LDT + ag) * 2;

    const int lA = laneA_off(lane);
    const int lB = laneB_off(lane);

    float acc[4][4][4];
    #pragma unroll
    for (int i = 0; i < 4; i++)
        #pragma unroll
        for (int j = 0; j < 4; j++)
            #pragma unroll
            for (int t = 0; t < 4; t++) acc[i][j][t] = 0.f;

    auto issue = [&](int c) {
        const uint32_t sb = sbase + (c % NST2) * STAGE_BY2;
        const int k0 = c * BK;
        cp16(sb + Q_AH * 2 + dA,  pAh + k0);
        cp16(sb + Q_AL * 2 + dA,  pAl + k0);
        cp16(sb + Q_BH * 2 + dA,  pB1h + k0);
        cp16(sb + Q_BH * 2 + dB2, pB2h + k0);
    };

    const int nc = K / BK;
    issue(0);
    asm volatile("cp.async.commit_group;");
    issue(1);
    asm volatile("cp.async.commit_group;");

    for (int c = 0; c < nc; ++c) {
        asm volatile("cp.async.wait_group 1;");
        __syncthreads();
        if (c + 2 < nc) issue(c + 2);
        asm volatile("cp.async.commit_group;");

        const uint32_t stb = sbase + (c % NST2) * STAGE_BY2;
        const uint32_t aH0 = stb + Q_AH * 2 + (wm * LDT + lA) * 2;
        const uint32_t aL0 = stb + Q_AL * 2 + (wm * LDT + lA) * 2;
        const uint32_t bH0 = stb + Q_BH * 2 + (wn * LDT + lB) * 2;
        #pragma unroll
        for (int ks = 0; ks < 2; ++ks) {
            const uint32_t ko = ks * 32;   // 16 halves = 32 bytes
            compute_ks2(acc, aH0 + ko, aL0 + ko, bH0 + ko);
        }
    }

    // ---------------- epilogue ----------------
    #pragma unroll
    for (int i = 0; i < 4; i++) {
        const int r0 = tm + wm + i * 16 + (lane >> 2);
        float bv0 = 0.f, bv1 = 0.f;
        if (HASBIAS) { bv0 = bias[r0]; bv1 = bias[r0 + 8]; }
        #pragma unroll
        for (int j = 0; j < 4; j++) {
            const int cc = tn + wn + j * 8 + (lane & 3) * 2;
            float d0 = acc[i][j][0] + bv0, d1 = acc[i][j][1] + bv0;
            float d2 = acc[i][j][2] + bv1, d3 = acc[i][j][3] + bv1;
            if (OUTMODE == 0) {
                float* cfp = Cf + (size_t)blockIdx.z * sC_;
                *reinterpret_cast<float2*>(&cfp[(size_t)r0 * ldc + cc])       = make_float2(d0, d1);
                *reinterpret_cast<float2*>(&cfp[(size_t)(r0 + 8) * ldc + cc]) = make_float2(d2, d3);
            } else if (OUTMODE == 1) {
                __half* chp = Ch + (size_t)blockIdx.z * sC_;
                __half* clp = Cl + (size_t)blockIdx.z * sC_;
                __half h0, h1, h2, h3, l0, l1, l2, l3;
                split2h(d0, h0, l0); split2h(d1, h1, l1);
                split2h(d2, h2, l2); split2h(d3, h3, l3);
                *reinterpret_cast<uint32_t*>(&chp[(size_t)r0 * ldc + cc])       = pack2h(h0, h1);
                *reinterpret_cast<uint32_t*>(&clp[(size_t)r0 * ldc + cc])       = pack2h(l0, l1);
                *reinterpret_cast<uint32_t*>(&chp[(size_t)(r0 + 8) * ldc + cc]) = pack2h(h2, h3);
                *reinterpret_cast<uint32_t*>(&clp[(size_t)(r0 + 8) * ldc + cc]) = pack2h(l2, l3);
            } else {
                __half* chp = Ch + (size_t)blockIdx.z * sC_;
                *reinterpret_cast<uint32_t*>(&chp[(size_t)r0 * ldc + cc]) =
                    pack2h(__float2half(d0), __float2half(d1));
                *reinterpret_cast<uint32_t*>(&chp[(size_t)(r0 + 8) * ldc + cc]) =
                    pack2h(__float2half(d2), __float2half(d3));
            }
        }
    }
}

// ================= S kernel: 128x128, 256 threads, 2-stage, 3-pass ========
#define SP_AH 0
#define SP_AL (128 * LDT)
#define SP_BH (256 * LDT)
#define SP_BL (384 * LDT)
#define STAGE_ELS (512 * LDT)
#define STAGE_BYS (STAGE_ELS * 2)             // 40960 B
#define NSTS 2
#define SMEM_BYS (NSTS * STAGE_BYS)           // 81920 B

__global__ __launch_bounds__(256)
void gemm_s(const __half* __restrict__ Ah, const __half* __restrict__ Al,
            const __half* __restrict__ Bh, const __half* __restrict__ Bl,
            float* __restrict__ Cf,
            int K, int lda, int ldb, int ldc,
            size_t sA_, size_t sB_, size_t sC_)
{
    extern __shared__ __half smem[];
    const int tid  = threadIdx.x;
    const int warp = tid >> 5;
    const int lane = tid & 31;
    const int wm   = (warp >> 2) * 64;
    const int wn   = (warp & 3) * 32;
    const int tm   = blockIdx.y * 128;
    const int tn   = blockIdx.x * 128;

    const __half* Ahb = Ah + (size_t)blockIdx.z * sA_;
    const __half* Alb = Al + (size_t)blockIdx.z * sA_;
    const __half* Bhb = Bh + (size_t)blockIdx.z * sB_;
    const __half* Blb = Bl + (size_t)blockIdx.z * sB_;

    const int lrow = tid >> 1;
    const int lg   = (tid & 1) * 16;
    const __half* pAh = Ahb + (size_t)(tm + lrow) * lda + lg;
    const __half* pAl = Alb + (size_t)(tm + lrow) * lda + lg;
    const __half* pBh = Bhb + (size_t)(tn + lrow) * ldb + lg;
    const __half* pBl = Blb + (size_t)(tn + lrow) * ldb + lg;
    const uint32_t sbase = smem_u32(smem);
    const uint32_t doff  = (lrow * LDT + lg) * 2;

    const int lA = laneA_off(lane);
    const int lB = laneB_off(lane);

    float acc[4][4][4];
    #pragma unroll
    for (int i = 0; i < 4; i++)
        #pragma unroll
        for (int j = 0; j < 4; j++)
            #pragma unroll
            for (int t = 0; t < 4; t++) acc[i][j][t] = 0.f;

    auto issue = [&](int c) {
        const uint32_t sb = sbase + (c & 1) * STAGE_BYS + doff;
        const int k0 = c * BK;
        cp16(sb + SP_AH * 2,      pAh + k0);
        cp16(sb + SP_AH * 2 + 16, pAh + k0 + 8);
        cp16(sb + SP_AL * 2,      pAl + k0);
        cp16(sb + SP_AL * 2 + 16, pAl + k0 + 8);
        cp16(sb + SP_BH * 2,      pBh + k0);
        cp16(sb + SP_BH * 2 + 16, pBh + k0 + 8);
        cp16(sb + SP_BL * 2,      pBl + k0);
        cp16(sb + SP_BL * 2 + 16, pBl + k0 + 8);
    };

    const int nc = K / BK;
    issue(0);
    asm volatile("cp.async.commit_group;");

    for (int c = 0; c < nc; ++c) {
        asm volatile("cp.async.wait_group 0;");
        __syncthreads();
        if (c + 1 < nc) issue(c + 1);
        asm volatile("cp.async.commit_group;");

        const uint32_t stb = sbase + (c & 1) * STAGE_BYS;
        const uint32_t aH0 = stb + SP_AH * 2 + (wm * LDT + lA) * 2;
        const uint32_t aL0 = stb + SP_AL * 2 + (wm * LDT + lA) * 2;
        const uint32_t bH0 = stb + SP_BH * 2 + (wn * LDT + lB) * 2;
        const uint32_t bL0 = stb + SP_BL * 2 + (wn * LDT + lB) * 2;
        #pragma unroll
        for (int ks = 0; ks < 2; ++ks) {
            const uint32_t ko = ks * 32;
            compute_ks3(acc, aH0 + ko, aL0 + ko, bH0 + ko, bL0 + ko);
        }
    }

    float* cfp = Cf + (size_t)blockIdx.z * sC_;
    #pragma unroll
    for (int i = 0; i < 4; i++) {
        const int r0 = tm + wm + i * 16 + (lane >> 2);
        #pragma unroll
        for (int j = 0; j < 4; j++) {
            const int cc = tn + wn + j * 8 + (lane & 3) * 2;
            *reinterpret_cast<float2*>(&cfp[(size_t)r0 * ldc + cc]) =
                make_float2(acc[i][j][0], acc[i][j][1]);
            *reinterpret_cast<float2*>(&cfp[(size_t)(r0 + 8) * ldc + cc]) =
                make_float2(acc[i][j][2], acc[i][j][3]);
        }
    }
}

// ------------- transpose fp32 [R,Cc] -> fp16 hi [Cc,R] ---------------------
__global__ void transpose_hi(const float* __restrict__ in,
                             __half* __restrict__ oh,
                             int R, int Cc, size_t sIn, size_t sOut)
{
    __shared__ float t[32][33];
    const float* ip = in + (size_t)blockIdx.z * sIn;
    int r0 = blockIdx.y * 32, c0 = blockIdx.x * 32;
    #pragma unroll
    for (int j = threadIdx.y; j < 32; j += 8)
        t[j][threadIdx.x] = ip[(size_t)(r0 + j) * Cc + c0 + threadIdx.x];
    __syncthreads();
    #pragma unroll
    for (int j = threadIdx.y; j < 32; j += 8) {
        size_t idx = (size_t)blockIdx.z * sOut + (size_t)(c0 + j) * R + r0 + threadIdx.x;
        oh[idx] = __float2half(t[threadIdx.x][j]);
    }
}

// ------------- transpose two fp16 planes: [R,Cc] -> [Cc,R] -----------------
__global__ void transpose_h2(const __half* __restrict__ ih,
                             const __half* __restrict__ il,
                             __half* __restrict__ oh,
                             __half* __restrict__ ol,
                             int R, int Cc, size_t sIn, size_t sOut)
{
    __shared__ __half th[32][34], tl[32][34];
    const __half* ihp = ih + (size_t)blockIdx.z * sIn;
    const __half* ilp = il + (size_t)blockIdx.z * sIn;
    int r0 = blockIdx.y * 32, c0 = blockIdx.x * 32;
    #pragma unroll
    for (int j = threadIdx.y; j < 32; j += 8) {
        size_t s = (size_t)(r0 + j) * Cc + c0 + threadIdx.x;
        th[j][threadIdx.x] = ihp[s];
        tl[j][threadIdx.x] = ilp[s];
    }
    __syncthreads();
    #pragma unroll
    for (int j = threadIdx.y; j < 32; j += 8) {
        size_t d = (size_t)blockIdx.z * sOut + (size_t)(c0 + j) * R + r0 + threadIdx.x;
        oh[d] = th[threadIdx.x][j];
        ol[d] = tl[threadIdx.x][j];
    }
}

// ------------- elementwise split fp32 -> fp16 hi/lo ------------------------
__global__ void split_w(const float* __restrict__ in,
                        __half* __restrict__ oh,
                        __half* __restrict__ ol, int n)
{
    int i = blockIdx.x * blockDim.x + threadIdx.x;
    if (i >= n) return;
    __half h, l;
    split2h(in[i], h, l);
    oh[i] = h;
    ol[i] = l;
}

// ------------- softmax (fp32 in, fp16 hi out), rows of 512 -----------------
__global__ void softmax_hi(const float* __restrict__ S,
                           __half* __restrict__ oh, float scale)
{
    int warp = (blockIdx.x * blockDim.x + threadIdx.x) >> 5;
    int lane = threadIdx.x & 31;
    if (warp >= B_ * C_) return;
    const float* row = S + (size_t)warp * C_;

    float vals[C_ / 32];
    float m = -1e30f;
    #pragma unroll
    for (int t = 0; t < C_ / 32; t++) {
        vals[t] = row[lane + t * 32] * scale;
        m = fmaxf(m, vals[t]);
    }
    #pragma unroll
    for (int o = 16; o; o >>= 1) m = fmaxf(m, __shfl_xor_sync(0xffffffffu, m, o));
    float s = 0.f;
    #pragma unroll
    for (int t = 0; t < C_ / 32; t++) { vals[t] = __expf(vals[t] - m); s += vals[t]; }
    #pragma unroll
    for (int o = 16; o; o >>= 1) s += __shfl_xor_sync(0xffffffffu, s, o);
    float inv = 1.f / s;
    #pragma unroll
    for (int t = 0; t < C_ / 32; t++)
        oh[(size_t)warp * C_ + lane + t * 32] = __float2half(vals[t] * inv);
}

// ---------------- launcher ----------------
extern "C" void kernel_launch(void* const* d_in, const int* in_sizes, int n_in,
                              void* d_out, int out_size)
{
    const float* x      = (const float*)d_in[0];
    const float* w_qkv  = (const float*)d_in[1];
    const float* b_qkv  = (const float*)d_in[2];
    const float* w_proj = (const float*)d_in[3];
    const float* b_proj = (const float*)d_in[4];
    float* out = (float*)d_out;

    __half *qh, *ql, *xTh, *vTh, *vTl, *ah, *wqh, *wql, *wph, *wpl;
    float *S;
    cudaGetSymbolAddress((void**)&qh,  g_qh);
    cudaGetSymbolAddress((void**)&ql,  g_ql);
    cudaGetSymbolAddress((void**)&xTh, g_xTh);
    cudaGetSymbolAddress((void**)&vTh, g_vTh);
    cudaGetSymbolAddress((void**)&vTl, g_vTl);
    cudaGetSymbolAddress((void**)&S,   g_S);
    cudaGetSymbolAddress((void**)&ah,  g_ah);
    cudaGetSymbolAddress((void**)&wqh, g_wqh);
    cudaGetSymbolAddress((void**)&wql, g_wql);
    cudaGetSymbolAddress((void**)&wph, g_wph);
    cudaGetSymbolAddress((void**)&wpl, g_wpl);

    cudaFuncSetAttribute(gemm_big<true,  1>, cudaFuncAttributeMaxDynamicSharedMemorySize, SMEM_BY2);
    cudaFuncSetAttribute(gemm_big<false, 2>, cudaFuncAttributeMaxDynamicSharedMemorySize, SMEM_BY2);
    cudaFuncSetAttribute(gemm_big<true,  0>, cudaFuncAttributeMaxDynamicSharedMemorySize, SMEM_BY2);
    cudaFuncSetAttribute(gemm_s, cudaFuncAttributeMaxDynamicSharedMemorySize, SMEM_BYS);

    const float scale = 1.0f / sqrtf((float)C_);
    dim3 tblk(32, 8);

    // 0) split weights -> fp16 hi/lo
    split_w<<<(O3 * C_ + 255) / 256, 256>>>(w_qkv, wqh, wql, O3 * C_);
    split_w<<<(C_ * C_ + 255) / 256, 256>>>(w_proj, wph, wpl, C_ * C_);

    // 1) xT hi: x[b,c,n] -> [b,n,c]
    transpose_hi<<<dim3(N_ / 32, C_ / 32, B_), tblk>>>(
        x, xTh, C_, N_, (size_t)C_ * N_, (size_t)N_ * C_);

    // 2) qkv = w_qkv @ xT^T + b  (2-pass) -> fp16 hi/lo
    gemm_big<true, 1><<<dim3(N_ / BN2, O3 / BM2, B_), 512, SMEM_BY2>>>(
        wqh, wql, xTh, nullptr, qh, ql, b_qkv,
        C_, C_, C_, N_,
        0, (size_t)N_ * C_, (size_t)O3 * N_);

    // 3) vT hi/lo: v[b,d,n] -> [b,n,d]
    transpose_h2<<<dim3(N_ / 32, C_ / 32, B_), tblk>>>(
        qh + (size_t)2 * C_ * N_, ql + (size_t)2 * C_ * N_, vTh, vTl,
        C_, N_, (size_t)O3 * N_, (size_t)N_ * C_);

    // 4) S = q @ k^T (3-pass, K=9216) -> fp32
    gemm_s<<<dim3(C_ / 128, C_ / 128, B_), 256, SMEM_BYS>>>(
        qh, ql, qh + (size_t)C_ * N_, ql + (size_t)C_ * N_, S,
        N_, N_, N_, C_,
        (size_t)O3 * N_, (size_t)O3 * N_, (size_t)C_ * C_);

    // 5) softmax -> attn hi
    softmax_hi<<<(B_ * C_ * 32 + 255) / 256, 256>>>(S, ah, scale);

    // 6) o1T[b,n,c] = vT[b,n,:] @ attn[b,c,:]  (2-pass) -> hi only (reuse xTh)
    gemm_big<false, 2><<<dim3(C_ / BN2, N_ / BM2, B_), 512, SMEM_BY2>>>(
        vTh, vTl, ah, nullptr, xTh, nullptr, nullptr,
        C_, C_, C_, C_,
        (size_t)N_ * C_, (size_t)C_ * C_, (size_t)N_ * C_);

    // 7) out = w_proj @ o1T^T + b  (2-pass) -> fp32
    gemm_big<true, 0><<<dim3(N_ / BN2, C_ / BM2, B_), 512, SMEM_BY2>>>(
        wph, wpl, xTh, out, nullptr, nullptr, b_proj,
        C_, C_, C_, N_,
        0, (size_t)N_ * C_, (size_t)C_ * N_);
}

// round 11
// speedup vs baseline: 1.6065x; 1.2387x over previous
#include <cuda_runtime.h>
#include <cuda_fp16.h>
#include <math.h>
#include <stdint.h>

// ---------------- problem constants ----------------
constexpr int B_ = 8, C_ = 512, H_ = 96, W_ = 96;
constexpr int N_ = H_ * W_;    // 9216
constexpr int O3 = 3 * C_;     // 1536

// ---------------- scratch: fp16 planes ----------------
__device__ __align__(256) __half g_qh [(size_t)B_ * O3 * N_];   // qkv hi
__device__ __align__(256) __half g_ql [(size_t)B_ * O3 * N_];   // qkv lo
__device__ __align__(256) __half g_xTh[(size_t)B_ * N_ * C_];   // xT hi; later o1T hi
__device__ __align__(256) __half g_vTh[(size_t)B_ * N_ * C_];
__device__ __align__(256) __half g_vTl[(size_t)B_ * N_ * C_];
__device__ __align__(256) float  g_S  [(size_t)B_ * C_ * C_];
__device__ __align__(256) __half g_ah [(size_t)B_ * C_ * C_];   // attn hi
__device__ __align__(256) __half g_wqh[(size_t)O3 * C_];
__device__ __align__(256) __half g_wph[(size_t)C_ * C_];
__device__ __align__(256) __half g_wpl[(size_t)C_ * C_];

// ---------------- common helpers ----------------
#define BK 32
#define LDT 40   // smem row stride in halves (BK + 8 pad)

__device__ __forceinline__ uint32_t smem_u32(const void* p) {
    uint32_t a;
    asm("{ .reg .u64 t; cvta.to.shared.u64 t, %1; cvt.u32.u64 %0, t; }"
        : "=r"(a) : "l"(p));
    return a;
}
__device__ __forceinline__ void cp16(uint32_t dst, const void* src) {
    asm volatile("cp.async.cg.shared.global [%0], [%1], 16;"
                 :: "r"(dst), "l"(src));
}
__device__ __forceinline__ void mma16816(float* d, const uint32_t* a,
                                         const uint32_t* b) {
    asm volatile(
        "mma.sync.aligned.m16n8k16.row.col.f32.f16.f16.f32 "
        "{%0,%1,%2,%3}, {%4,%5,%6,%7}, {%8,%9}, {%0,%1,%2,%3};"
        : "+f"(d[0]), "+f"(d[1]), "+f"(d[2]), "+f"(d[3])
        : "r"(a[0]), "r"(a[1]), "r"(a[2]), "r"(a[3]), "r"(b[0]), "r"(b[1]));
}
__device__ __forceinline__ void ldm4(uint32_t* r, uint32_t a) {
    asm volatile("ldmatrix.sync.aligned.m8n8.x4.shared.b16 {%0,%1,%2,%3}, [%4];"
        : "=r"(r[0]), "=r"(r[1]), "=r"(r[2]), "=r"(r[3]) : "r"(a));
}
__device__ __forceinline__ uint32_t pack2h(__half a, __half b) {
    return (uint32_t)__half_as_ushort(a) |
           ((uint32_t)__half_as_ushort(b) << 16);
}
__device__ __forceinline__ void split2h(float f, __half& h, __half& l) {
    h = __float2half(f);
    l = __float2half(f - __half2float(h));
}

// lane offsets (half elem units) for ldmatrix addressing
__device__ __forceinline__ int laneA_off(int lane) {
    return ((lane & 7) + ((lane >> 3) & 1) * 8) * LDT + ((lane >> 4) & 1) * 8;
}
__device__ __forceinline__ int laneB_off(int lane) {
    return ((lane & 7) + ((lane >> 4) & 1) * 8) * LDT + ((lane >> 3) & 1) * 8;
}

// 1-pass compute body: ah * bh
__device__ __forceinline__ void compute_ks1(float acc[4][4][4],
                                            uint32_t aHi, uint32_t bHi)
{
    uint32_t ah[4][4], bh[2][4];
    #pragma unroll
    for (int i = 0; i < 4; i++) ldm4(ah[i], aHi + i * (16 * LDT * 2));
    #pragma unroll
    for (int jp = 0; jp < 2; jp++) ldm4(bh[jp], bHi + jp * (16 * LDT * 2));
    #pragma unroll
    for (int i = 0; i < 4; i++) {
        mma16816(acc[i][0], ah[i], bh[0]);
        mma16816(acc[i][1], ah[i], bh[0] + 2);
        mma16816(acc[i][2], ah[i], bh[1]);
        mma16816(acc[i][3], ah[i], bh[1] + 2);
    }
}

// 2-pass compute body: (ah + al) * bh
__device__ __forceinline__ void compute_ks2(float acc[4][4][4],
                                            uint32_t aHi, uint32_t aLo,
                                            uint32_t bHi)
{
    uint32_t ah[4][4], al_[4][4], bh[2][4];
    #pragma unroll
    for (int i = 0; i < 4; i++) ldm4(ah[i], aHi + i * (16 * LDT * 2));
    #pragma unroll
    for (int jp = 0; jp < 2; jp++) ldm4(bh[jp], bHi + jp * (16 * LDT * 2));
    #pragma unroll
    for (int i = 0; i < 4; i++) {
        ldm4(al_[i], aLo + i * (16 * LDT * 2));
        mma16816(acc[i][0], ah[i], bh[0]);
        mma16816(acc[i][1], ah[i], bh[0] + 2);
        mma16816(acc[i][2], ah[i], bh[1]);
        mma16816(acc[i][3], ah[i], bh[1] + 2);
    }
    #pragma unroll
    for (int i = 0; i < 4; i++) {
        mma16816(acc[i][0], al_[i], bh[0]);
        mma16816(acc[i][1], al_[i], bh[0] + 2);
        mma16816(acc[i][2], al_[i], bh[1]);
        mma16816(acc[i][3], al_[i], bh[1] + 2);
    }
}

// ============== BIG kernel: 128x256, 512 thr, 3-stage =====================
// OUTMODE: 0 = f32, 1 = split hi/lo fp16, 2 = hi-only fp16
// PASSES:  1 = ah*bh ; 2 = (ah+al)*bh
#define BM2 128
#define BN2 256
#define NST2 3
#define Q_AH 0
#define Q_AL (128 * LDT)
#define Q_BH (256 * LDT)
#define STAGE_EL2 (512 * LDT)
#define STAGE_BY2 (STAGE_EL2 * 2)             // 40960 B
#define SMEM_BY2 (NST2 * STAGE_BY2)           // 122880 B

template<bool HASBIAS, int OUTMODE, int PASSES>
__global__ __launch_bounds__(512)
void gemm_big(const __half* __restrict__ Ah, const __half* __restrict__ Al,
              const __half* __restrict__ Bh,
              float* __restrict__ Cf,
              __half* __restrict__ Ch, __half* __restrict__ Cl,
              const float* __restrict__ bias,
              int K, int lda, int ldb, int ldc,
              size_t sA_, size_t sB_, size_t sC_)
{
    extern __shared__ __half smem[];
    const int tid  = threadIdx.x;
    const int warp = tid >> 5;
    const int lane = tid & 31;
    const int wm   = (warp >> 3) * 64;   // 2 warps in M
    const int wn   = (warp & 7) * 32;    // 8 warps in N
    const int tm   = blockIdx.y * BM2;
    const int tn   = blockIdx.x * BN2;

    const __half* Ahb = Ah + (size_t)blockIdx.z * sA_;
    const __half* Alb = (PASSES == 2) ? Al + (size_t)blockIdx.z * sA_ : nullptr;
    const __half* Bhb = Bh + (size_t)blockIdx.z * sB_;

    const int arow = tid >> 2, ag = (tid & 3) * 8;

    const __half* pAh  = Ahb + (size_t)(tm + arow) * lda + ag;
    const __half* pAl  = (PASSES == 2) ? Alb + (size_t)(tm + arow) * lda + ag : nullptr;
    const __half* pB1h = Bhb + (size_t)(tn + arow) * ldb + ag;
    const __half* pB2h = Bhb + (size_t)(tn + 128 + arow) * ldb + ag;

    const uint32_t sbase = smem_u32(smem);
    const uint32_t dA  = (arow * LDT + ag) * 2;
    const uint32_t dB2 = ((arow + 128) * LDT + ag) * 2;

    const int lA = laneA_off(lane);
    const int lB = laneB_off(lane);

    float acc[4][4][4];
    #pragma unroll
    for (int i = 0; i < 4; i++)
        #pragma unroll
        for (int j = 0; j < 4; j++)
            #pragma unroll
            for (int t = 0; t < 4; t++) acc[i][j][t] = 0.f;

    auto issue = [&](int c) {
        const uint32_t sb = sbase + (c % NST2) * STAGE_BY2;
        const int k0 = c * BK;
        cp16(sb + Q_AH * 2 + dA,  pAh + k0);
        if (PASSES == 2) cp16(sb + Q_AL * 2 + dA, pAl + k0);
        cp16(sb + Q_BH * 2 + dA,  pB1h + k0);
        cp16(sb + Q_BH * 2 + dB2, pB2h + k0);
    };

    const int nc = K / BK;
    issue(0);
    asm volatile("cp.async.commit_group;");
    issue(1);
    asm volatile("cp.async.commit_group;");

    for (int c = 0; c < nc; ++c) {
        asm volatile("cp.async.wait_group 1;");
        __syncthreads();
        if (c + 2 < nc) issue(c + 2);
        asm volatile("cp.async.commit_group;");

        const uint32_t stb = sbase + (c % NST2) * STAGE_BY2;
        const uint32_t aH0 = stb + Q_AH * 2 + (wm * LDT + lA) * 2;
        const uint32_t aL0 = stb + Q_AL * 2 + (wm * LDT + lA) * 2;
        const uint32_t bH0 = stb + Q_BH * 2 + (wn * LDT + lB) * 2;
        #pragma unroll
        for (int ks = 0; ks < 2; ++ks) {
            const uint32_t ko = ks * 32;   // 16 halves = 32 bytes
            if (PASSES == 2) compute_ks2(acc, aH0 + ko, aL0 + ko, bH0 + ko);
            else             compute_ks1(acc, aH0 + ko, bH0 + ko);
        }
    }

    // ---------------- epilogue ----------------
    #pragma unroll
    for (int i = 0; i < 4; i++) {
        const int r0 = tm + wm + i * 16 + (lane >> 2);
        float bv0 = 0.f, bv1 = 0.f;
        if (HASBIAS) { bv0 = bias[r0]; bv1 = bias[r0 + 8]; }
        #pragma unroll
        for (int j = 0; j < 4; j++) {
            const int cc = tn + wn + j * 8 + (lane & 3) * 2;
            float d0 = acc[i][j][0] + bv0, d1 = acc[i][j][1] + bv0;
            float d2 = acc[i][j][2] + bv1, d3 = acc[i][j][3] + bv1;
            if (OUTMODE == 0) {
                float* cfp = Cf + (size_t)blockIdx.z * sC_;
                *reinterpret_cast<float2*>(&cfp[(size_t)r0 * ldc + cc])       = make_float2(d0, d1);
                *reinterpret_cast<float2*>(&cfp[(size_t)(r0 + 8) * ldc + cc]) = make_float2(d2, d3);
            } else if (OUTMODE == 1) {
                __half* chp = Ch + (size_t)blockIdx.z * sC_;
                __half* clp = Cl + (size_t)blockIdx.z * sC_;
                __half h0, h1, h2, h3, l0, l1, l2, l3;
                split2h(d0, h0, l0); split2h(d1, h1, l1);
                split2h(d2, h2, l2); split2h(d3, h3, l3);
                *reinterpret_cast<uint32_t*>(&chp[(size_t)r0 * ldc + cc])       = pack2h(h0, h1);
                *reinterpret_cast<uint32_t*>(&clp[(size_t)r0 * ldc + cc])       = pack2h(l0, l1);
                *reinterpret_cast<uint32_t*>(&chp[(size_t)(r0 + 8) * ldc + cc]) = pack2h(h2, h3);
                *reinterpret_cast<uint32_t*>(&clp[(size_t)(r0 + 8) * ldc + cc]) = pack2h(l2, l3);
            } else {
                __half* chp = Ch + (size_t)blockIdx.z * sC_;
                *reinterpret_cast<uint32_t*>(&chp[(size_t)r0 * ldc + cc]) =
                    pack2h(__float2half(d0), __float2half(d1));
                *reinterpret_cast<uint32_t*>(&chp[(size_t)(r0 + 8) * ldc + cc]) =
                    pack2h(__float2half(d2), __float2half(d3));
            }
        }
    }
}

// ====== S kernel: 128x128, 256 threads, 2-stage, 2-pass (q hi/lo * k hi) ===
#define SP_AH 0
#define SP_AL (128 * LDT)
#define SP_BH (256 * LDT)
#define STAGE_ELS (384 * LDT)
#define STAGE_BYS (STAGE_ELS * 2)             // 30720 B
#define NSTS 2
#define SMEM_BYS (NSTS * STAGE_BYS)           // 61440 B

__global__ __launch_bounds__(256)
void gemm_s(const __half* __restrict__ Ah, const __half* __restrict__ Al,
            const __half* __restrict__ Bh,
            float* __restrict__ Cf,
            int K, int lda, int ldb, int ldc,
            size_t sA_, size_t sB_, size_t sC_)
{
    extern __shared__ __half smem[];
    const int tid  = threadIdx.x;
    const int warp = tid >> 5;
    const int lane = tid & 31;
    const int wm   = (warp >> 2) * 64;
    const int wn   = (warp & 3) * 32;
    const int tm   = blockIdx.y * 128;
    const int tn   = blockIdx.x * 128;

    const __half* Ahb = Ah + (size_t)blockIdx.z * sA_;
    const __half* Alb = Al + (size_t)blockIdx.z * sA_;
    const __half* Bhb = Bh + (size_t)blockIdx.z * sB_;

    const int lrow = tid >> 1;
    const int lg   = (tid & 1) * 16;
    const __half* pAh = Ahb + (size_t)(tm + lrow) * lda + lg;
    const __half* pAl = Alb + (size_t)(tm + lrow) * lda + lg;
    const __half* pBh = Bhb + (size_t)(tn + lrow) * ldb + lg;
    const uint32_t sbase = smem_u32(smem);
    const uint32_t doff  = (lrow * LDT + lg) * 2;

    const int lA = laneA_off(lane);
    const int lB = laneB_off(lane);

    float acc[4][4][4];
    #pragma unroll
    for (int i = 0; i < 4; i++)
        #pragma unroll
        for (int j = 0; j < 4; j++)
            #pragma unroll
            for (int t = 0; t < 4; t++) acc[i][j][t] = 0.f;

    auto issue = [&](int c) {
        const uint32_t sb = sbase + (c & 1) * STAGE_BYS + doff;
        const int k0 = c * BK;
        cp16(sb + SP_AH * 2,      pAh + k0);
        cp16(sb + SP_AH * 2 + 16, pAh + k0 + 8);
        cp16(sb + SP_AL * 2,      pAl + k0);
        cp16(sb + SP_AL * 2 + 16, pAl + k0 + 8);
        cp16(sb + SP_BH * 2,      pBh + k0);
        cp16(sb + SP_BH * 2 + 16, pBh + k0 + 8);
    };

    const int nc = K / BK;
    issue(0);
    asm volatile("cp.async.commit_group;");

    for (int c = 0; c < nc; ++c) {
        asm volatile("cp.async.wait_group 0;");
        __syncthreads();
        if (c + 1 < nc) issue(c + 1);
        asm volatile("cp.async.commit_group;");

        const uint32_t stb = sbase + (c & 1) * STAGE_BYS;
        const uint32_t aH0 = stb + SP_AH * 2 + (wm * LDT + lA) * 2;
        const uint32_t aL0 = stb + SP_AL * 2 + (wm * LDT + lA) * 2;
        const uint32_t bH0 = stb + SP_BH * 2 + (wn * LDT + lB) * 2;
        #pragma unroll
        for (int ks = 0; ks < 2; ++ks) {
            const uint32_t ko = ks * 32;
            compute_ks2(acc, aH0 + ko, aL0 + ko, bH0 + ko);
        }
    }

    float* cfp = Cf + (size_t)blockIdx.z * sC_;
    #pragma unroll
    for (int i = 0; i < 4; i++) {
        const int r0 = tm + wm + i * 16 + (lane >> 2);
        #pragma unroll
        for (int j = 0; j < 4; j++) {
            const int cc = tn + wn + j * 8 + (lane & 3) * 2;
            *reinterpret_cast<float2*>(&cfp[(size_t)r0 * ldc + cc]) =
                make_float2(acc[i][j][0], acc[i][j][1]);
            *reinterpret_cast<float2*>(&cfp[(size_t)(r0 + 8) * ldc + cc]) =
                make_float2(acc[i][j][2], acc[i][j][3]);
        }
    }
}

// ------------- transpose fp32 [R,Cc] -> fp16 hi [Cc,R] ---------------------
__global__ void transpose_hi(const float* __restrict__ in,
                             __half* __restrict__ oh,
                             int R, int Cc, size_t sIn, size_t sOut)
{
    __shared__ float t[32][33];
    const float* ip = in + (size_t)blockIdx.z * sIn;
    int r0 = blockIdx.y * 32, c0 = blockIdx.x * 32;
    #pragma unroll
    for (int j = threadIdx.y; j < 32; j += 8)
        t[j][threadIdx.x] = ip[(size_t)(r0 + j) * Cc + c0 + threadIdx.x];
    __syncthreads();
    #pragma unroll
    for (int j = threadIdx.y; j < 32; j += 8) {
        size_t idx = (size_t)blockIdx.z * sOut + (size_t)(c0 + j) * R + r0 + threadIdx.x;
        oh[idx] = __float2half(t[threadIdx.x][j]);
    }
}

// ------------- transpose two fp16 planes: [R,Cc] -> [Cc,R] -----------------
__global__ void transpose_h2(const __half* __restrict__ ih,
                             const __half* __restrict__ il,
                             __half* __restrict__ oh,
                             __half* __restrict__ ol,
                             int R, int Cc, size_t sIn, size_t sOut)
{
    __shared__ __half th[32][34], tl[32][34];
    const __half* ihp = ih + (size_t)blockIdx.z * sIn;
    const __half* ilp = il + (size_t)blockIdx.z * sIn;
    int r0 = blockIdx.y * 32, c0 = blockIdx.x * 32;
    #pragma unroll
    for (int j = threadIdx.y; j < 32; j += 8) {
        size_t s = (size_t)(r0 + j) * Cc + c0 + threadIdx.x;
        th[j][threadIdx.x] = ihp[s];
        tl[j][threadIdx.x] = ilp[s];
    }
    __syncthreads();
    #pragma unroll
    for (int j = threadIdx.y; j < 32; j += 8) {
        size_t d = (size_t)blockIdx.z * sOut + (size_t)(c0 + j) * R + r0 + threadIdx.x;
        oh[d] = th[threadIdx.x][j];
        ol[d] = tl[threadIdx.x][j];
    }
}

// ------------- elementwise casts ------------------------------------------
__global__ void split_w(const float* __restrict__ in,
                        __half* __restrict__ oh,
                        __half* __restrict__ ol, int n)
{
    int i = blockIdx.x * blockDim.x + threadIdx.x;
    if (i >= n) return;
    __half h, l;
    split2h(in[i], h, l);
    oh[i] = h;
    ol[i] = l;
}
__global__ void cast_hi(const float* __restrict__ in,
                        __half* __restrict__ oh, int n)
{
    int i = blockIdx.x * blockDim.x + threadIdx.x;
    if (i >= n) return;
    oh[i] = __float2half(in[i]);
}

// ------------- softmax (fp32 in, fp16 hi out), rows of 512 -----------------
__global__ void softmax_hi(const float* __restrict__ S,
                           __half* __restrict__ oh, float scale)
{
    int warp = (blockIdx.x * blockDim.x + threadIdx.x) >> 5;
    int lane = threadIdx.x & 31;
    if (warp >= B_ * C_) return;
    const float* row = S + (size_t)warp * C_;

    float vals[C_ / 32];
    float m = -1e30f;
    #pragma unroll
    for (int t = 0; t < C_ / 32; t++) {
        vals[t] = row[lane + t * 32] * scale;
        m = fmaxf(m, vals[t]);
    }
    #pragma unroll
    for (int o = 16; o; o >>= 1) m = fmaxf(m, __shfl_xor_sync(0xffffffffu, m, o));
    float s = 0.f;
    #pragma unroll
    for (int t = 0; t < C_ / 32; t++) { vals[t] = __expf(vals[t] - m); s += vals[t]; }
    #pragma unroll
    for (int o = 16; o; o >>= 1) s += __shfl_xor_sync(0xffffffffu, s, o);
    float inv = 1.f / s;
    #pragma unroll
    for (int t = 0; t < C_ / 32; t++)
        oh[(size_t)warp * C_ + lane + t * 32] = __float2half(vals[t] * inv);
}

// ---------------- launcher ----------------
extern "C" void kernel_launch(void* const* d_in, const int* in_sizes, int n_in,
                              void* d_out, int out_size)
{
    const float* x      = (const float*)d_in[0];
    const float* w_qkv  = (const float*)d_in[1];
    const float* b_qkv  = (const float*)d_in[2];
    const float* w_proj = (const float*)d_in[3];
    const float* b_proj = (const float*)d_in[4];
    float* out = (float*)d_out;

    __half *qh, *ql, *xTh, *vTh, *vTl, *ah, *wqh, *wph, *wpl;
    float *S;
    cudaGetSymbolAddress((void**)&qh,  g_qh);
    cudaGetSymbolAddress((void**)&ql,  g_ql);
    cudaGetSymbolAddress((void**)&xTh, g_xTh);
    cudaGetSymbolAddress((void**)&vTh, g_vTh);
    cudaGetSymbolAddress((void**)&vTl, g_vTl);
    cudaGetSymbolAddress((void**)&S,   g_S);
    cudaGetSymbolAddress((void**)&ah,  g_ah);
    cudaGetSymbolAddress((void**)&wqh, g_wqh);
    cudaGetSymbolAddress((void**)&wph, g_wph);
    cudaGetSymbolAddress((void**)&wpl, g_wpl);

    cudaFuncSetAttribute(gemm_big<true,  1, 1>, cudaFuncAttributeMaxDynamicSharedMemorySize, SMEM_BY2);
    cudaFuncSetAttribute(gemm_big<false, 2, 2>, cudaFuncAttributeMaxDynamicSharedMemorySize, SMEM_BY2);
    cudaFuncSetAttribute(gemm_big<true,  0, 2>, cudaFuncAttributeMaxDynamicSharedMemorySize, SMEM_BY2);
    cudaFuncSetAttribute(gemm_s, cudaFuncAttributeMaxDynamicSharedMemorySize, SMEM_BYS);

    const float scale = 1.0f / sqrtf((float)C_);
    dim3 tblk(32, 8);

    // 0) weights: qkv hi only (1-pass GEMM), proj hi/lo (2-pass GEMM)
    cast_hi<<<(O3 * C_ + 255) / 256, 256>>>(w_qkv, wqh, O3 * C_);
    split_w<<<(C_ * C_ + 255) / 256, 256>>>(w_proj, wph, wpl, C_ * C_);

    // 1) xT hi: x[b,c,n] -> [b,n,c]
    transpose_hi<<<dim3(N_ / 32, C_ / 32, B_), tblk>>>(
        x, xTh, C_, N_, (size_t)C_ * N_, (size_t)N_ * C_);

    // 2) qkv = w_qkv @ xT^T + b  (1-pass) -> fp16 hi/lo
    gemm_big<true, 1, 1><<<dim3(N_ / BN2, O3 / BM2, B_), 512, SMEM_BY2>>>(
        wqh, nullptr, xTh, nullptr, qh, ql, b_qkv,
        C_, C_, C_, N_,
        0, (size_t)N_ * C_, (size_t)O3 * N_);

    // 3) vT hi/lo: v[b,d,n] -> [b,n,d]
    transpose_h2<<<dim3(N_ / 32, C_ / 32, B_), tblk>>>(
        qh + (size_t)2 * C_ * N_, ql + (size_t)2 * C_ * N_, vTh, vTl,
        C_, N_, (size_t)O3 * N_, (size_t)N_ * C_);

    // 4) S = q @ k^T (2-pass, K=9216) -> fp32
    gemm_s<<<dim3(C_ / 128, C_ / 128, B_), 256, SMEM_BYS>>>(
        qh, ql, qh + (size_t)C_ * N_, S,
        N_, N_, N_, C_,
        (size_t)O3 * N_, (size_t)O3 * N_, (size_t)C_ * C_);

    // 5) softmax -> attn hi
    softmax_hi<<<(B_ * C_ * 32 + 255) / 256, 256>>>(S, ah, scale);

    // 6) o1T[b,n,c] = vT[b,n,:] @ attn[b,c,:]  (2-pass) -> hi only (reuse xTh)
    gemm_big<false, 2, 2><<<dim3(C_ / BN2, N_ / BM2, B_), 512, SMEM_BY2>>>(
        vTh, vTl, ah, nullptr, xTh, nullptr, nullptr,
        C_, C_, C_, C_,
        (size_t)N_ * C_, (size_t)C_ * C_, (size_t)N_ * C_);

    // 7) out = w_proj @ o1T^T + b  (2-pass) -> fp32
    gemm_big<true, 0, 2><<<dim3(N_ / BN2, C_ / BM2, B_), 512, SMEM_BY2>>>(
        wph, wpl, xTh, out, nullptr, nullptr, b_proj,
        C_, C_, C_, N_,
        0, (size_t)N_ * C_, (size_t)C_ * N_);
}